// round 3
// baseline (speedup 1.0000x reference)
#include <cuda_runtime.h>

// FourierBlock: B=32, L=2048, H=8, E=64, MODES=64
// y = irfft( place_low64( einsum('bhim,hiom', gather(rfft(q^T), index), W) ), n=L )
//
// Implemented as 3 dense contractions (no FFT needed; only 64 modes live):
//  K1: X[b,h,i,(re|im)m] = q^T @ [cos|-sin](2*pi*idx[m]*l/L)       [16384x2048]@[2048x128]
//  K2: O[b,h,o,m] = sum_i X[b,h,i,m] * (Wr + i Wi)[h,i,o,m]        small
//  K3: y[b,h,o,l] = sum_m scaled [cos|-sin](2*pi*m*l/L) combo      [16384x128]@[128x2048]

#define NB 32
#define NL 2048
#define NH 8
#define NE 64
#define NM 64

// ---------------- scratch (device globals; no allocs allowed) ----------------
__device__ float g_FB[NL * 128];                 // forward basis [l][k]  k<64: cos, k>=64: -sin (freq=index[k%64])
__device__ float g_IB[128 * NL];                 // inverse basis [k][l]  with 1/L and factor-2 folded in
__device__ float g_WtR[NH * NM * NE * NE];       // [h][m][i][o]
__device__ float g_WtI[NH * NM * NE * NE];
__device__ float g_XF[2 * NB * NH * 128 * NE];   // [part][b][h][k][e]  (K split into 2 halves over l)
__device__ float g_O2[NB * NH * 128 * NE];       // [b][h][k][o]  k<64: re(m=k), k>=64: im(m=k-64)

// ---------------- K0a: basis tables ----------------
__global__ __launch_bounds__(256) void k_basis(const int* __restrict__ index) {
    int t = blockIdx.x * blockDim.x + threadIdx.x;     // 0..262143
    if (t >= NL * 128) return;
    int l = t >> 7;
    int k = t & 127;
    int kf = k & 63;

    // forward: freq = index[kf]
    int f = index[kf];
    int p = (f * l) & (NL - 1);                        // exact integer phase
    float s, c;
    sincospif((float)p * (1.0f / 1024.0f), &s, &c);    // angle = 2*pi*p/2048 = pi*p/1024
    g_FB[t] = (k < 64) ? c : -s;

    // inverse: freq = kf (modes placed in slots 0..63), ducc c2r convention:
    //   y_l = (1/L)[Re X0 + 2*sum_{f>=1}(Re X_f cos - Im X_f sin)]
    int p2 = (kf * l) & (NL - 1);
    sincospif((float)p2 * (1.0f / 1024.0f), &s, &c);
    float amp = (kf == 0) ? ((k < 64) ? (1.0f / (float)NL) : 0.0f)
                          : (2.0f / (float)NL);
    g_IB[k * NL + l] = (k < 64) ? amp * c : -amp * s;
}

// ---------------- K0b: transpose W[h][i][o][m] -> Wt[h][m][i][o] ----------------
__global__ __launch_bounds__(256) void k_wt(const float* __restrict__ wr,
                                            const float* __restrict__ wi) {
    __shared__ float sm[64][65];
    int h = blockIdx.x >> 6;
    int i = blockIdx.x & 63;
    int t = threadIdx.x;
    const float* src = wr + (size_t)((h * 64 + i) * 64) * 64;   // [o][m] slab, m contiguous
    float* dst = g_WtR;
#pragma unroll
    for (int pass = 0; pass < 2; pass++) {
#pragma unroll
        for (int r = 0; r < 16; r++) {
            int idx = r * 256 + t;
            sm[idx >> 6][idx & 63] = src[idx];                  // sm[o][m], coalesced read
        }
        __syncthreads();
#pragma unroll
        for (int r = 0; r < 16; r++) {
            int idx = r * 256 + t;
            int m = idx >> 6, o = idx & 63;
            dst[(size_t)((h * 64 + m) * 64 + i) * 64 + o] = sm[o][m];  // coalesced write in o
        }
        __syncthreads();
        src = wi + (size_t)((h * 64 + i) * 64) * 64;
        dst = g_WtI;
    }
}

// ---------------- K1: forward DFT  per (b,h,part): [64e x 1024l] @ [1024l x 128k] ----------------
__global__ __launch_bounds__(256) void k_fwd(const float* __restrict__ q) {
    __shared__ __align__(16) float As[32][64];    // [l][e]
    __shared__ __align__(16) float Bs[32][128];   // [l][k]
    int bh = blockIdx.x;                          // b*8+h
    int b = bh >> 3, h = bh & 7;
    int p = blockIdx.y;                           // K-split half
    int t = threadIdx.x;
    int tx = t & 15, ty = t >> 4;

    float acc[4][8];
#pragma unroll
    for (int e = 0; e < 4; e++)
#pragma unroll
        for (int j = 0; j < 8; j++) acc[e][j] = 0.0f;

    // q[b,l,h,e] = q[ b*L*H*E + l*H*E + h*E + e ]
    const float* qb = q + (size_t)b * (NL * NH * NE) + h * NE + (size_t)p * 1024 * (NH * NE);
    const float* fb = g_FB + (size_t)p * 1024 * 128;

    for (int lt = 0; lt < 32; lt++) {
#pragma unroll
        for (int r = 0; r < 2; r++) {             // 32x64 A tile
            int f2 = r * 256 + t;
            int l = f2 >> 4, e4 = (f2 & 15) * 4;
            *(float4*)&As[l][e4] = *(const float4*)&qb[(size_t)(lt * 32 + l) * (NH * NE) + e4];
        }
#pragma unroll
        for (int r = 0; r < 4; r++) {             // 32x128 B tile
            int f2 = r * 256 + t;
            int l = f2 >> 5, k4 = (f2 & 31) * 4;
            *(float4*)&Bs[l][k4] = *(const float4*)&fb[(size_t)(lt * 32 + l) * 128 + k4];
        }
        __syncthreads();
#pragma unroll
        for (int l = 0; l < 32; l++) {
            float4 a  = *(float4*)&As[l][ty * 4];
            float4 b0 = *(float4*)&Bs[l][tx * 4];        // k = tx*4 + j       (j<4)
            float4 b1 = *(float4*)&Bs[l][64 + tx * 4];   // k = 64 + tx*4 + j  (j>=4)
            float av[4] = {a.x, a.y, a.z, a.w};
            float bv[8] = {b0.x, b0.y, b0.z, b0.w, b1.x, b1.y, b1.z, b1.w};
#pragma unroll
            for (int e = 0; e < 4; e++)
#pragma unroll
                for (int j = 0; j < 8; j++) acc[e][j] += av[e] * bv[j];
        }
        __syncthreads();
    }

    float* xf = g_XF + (size_t)(p * (NB * NH) + bh) * 128 * NE;
#pragma unroll
    for (int j = 0; j < 8; j++) {
        int k = (j < 4) ? (tx * 4 + j) : (64 + tx * 4 + (j - 4));
        *(float4*)&xf[k * NE + ty * 4] = make_float4(acc[0][j], acc[1][j], acc[2][j], acc[3][j]);
    }
}

// ---------------- K2: mode mixing  per (h,m): [32b x 64i] @ complex [64i x 64o] ----------------
__global__ __launch_bounds__(256) void k_mix() {
    __shared__ float Xr[32][64];
    __shared__ float Xi[32][64];
    __shared__ float Wr[64][64];
    __shared__ float Wi[64][64];
    int h = blockIdx.x >> 6;
    int m = blockIdx.x & 63;
    int t = threadIdx.x;

#pragma unroll
    for (int r = 0; r < 8; r++) {
        int idx = r * 256 + t;
        int b = idx >> 6, i = idx & 63;
        size_t base0 = ((size_t)(b * 8 + h) * 128);
        size_t base1 = ((size_t)(NB * NH + b * 8 + h) * 128);
        Xr[b][i] = g_XF[(base0 + m) * NE + i] + g_XF[(base1 + m) * NE + i];
        Xi[b][i] = g_XF[(base0 + 64 + m) * NE + i] + g_XF[(base1 + 64 + m) * NE + i];
    }
#pragma unroll
    for (int r = 0; r < 16; r++) {
        int idx = r * 256 + t;
        int i = idx >> 6, o = idx & 63;
        size_t wbase = (size_t)((h * 64 + m) * 64 + i) * 64 + o;
        Wr[i][o] = g_WtR[wbase];
        Wi[i][o] = g_WtI[wbase];
    }
    __syncthreads();

    int b = t >> 3;
    int og = (t & 7) * 8;
    float ar[8], ai[8];
#pragma unroll
    for (int j = 0; j < 8; j++) { ar[j] = 0.0f; ai[j] = 0.0f; }

    for (int i = 0; i < 64; i++) {
        float xr = Xr[b][i], xi = Xi[b][i];
#pragma unroll
        for (int j = 0; j < 8; j++) {
            float wr = Wr[i][og + j], wi = Wi[i][og + j];
            ar[j] += xr * wr - xi * wi;
            ai[j] += xr * wi + xi * wr;
        }
    }

    float* o2r = g_O2 + ((size_t)(b * 8 + h) * 128 + m) * NE + og;   // k=m (re)
    float* o2i = o2r + 64 * NE;                                      // k=64+m (im)
    *(float4*)&o2r[0] = make_float4(ar[0], ar[1], ar[2], ar[3]);
    *(float4*)&o2r[4] = make_float4(ar[4], ar[5], ar[6], ar[7]);
    *(float4*)&o2i[0] = make_float4(ai[0], ai[1], ai[2], ai[3]);
    *(float4*)&o2i[4] = make_float4(ai[4], ai[5], ai[6], ai[7]);
}

// ---------------- K3: inverse  per (b,h,ltile): [64o x 128k] @ [128k x 128l] ----------------
__global__ __launch_bounds__(256) void k_inv(float* __restrict__ out) {
    __shared__ __align__(16) float As[32][64];    // [k][o]
    __shared__ __align__(16) float Bs[32][128];   // [k][l]
    int bh = blockIdx.x;
    int l0 = blockIdx.y * 128;
    int t = threadIdx.x;
    int tx = t & 15, ty = t >> 4;

    float acc[4][8];
#pragma unroll
    for (int e = 0; e < 4; e++)
#pragma unroll
        for (int j = 0; j < 8; j++) acc[e][j] = 0.0f;

    const float* a_src = g_O2 + (size_t)bh * 128 * NE;

    for (int kt = 0; kt < 4; kt++) {
#pragma unroll
        for (int r = 0; r < 2; r++) {             // 32x64 A tile
            int f2 = r * 256 + t;
            int kk = f2 >> 4, o4 = (f2 & 15) * 4;
            *(float4*)&As[kk][o4] = *(const float4*)&a_src[(size_t)(kt * 32 + kk) * NE + o4];
        }
#pragma unroll
        for (int r = 0; r < 4; r++) {             // 32x128 B tile
            int f2 = r * 256 + t;
            int kk = f2 >> 5, l4 = (f2 & 31) * 4;
            *(float4*)&Bs[kk][l4] = *(const float4*)&g_IB[(size_t)(kt * 32 + kk) * NL + l0 + l4];
        }
        __syncthreads();
#pragma unroll
        for (int kk = 0; kk < 32; kk++) {
            float4 a  = *(float4*)&As[kk][ty * 4];
            float4 b0 = *(float4*)&Bs[kk][tx * 4];
            float4 b1 = *(float4*)&Bs[kk][64 + tx * 4];
            float av[4] = {a.x, a.y, a.z, a.w};
            float bv[8] = {b0.x, b0.y, b0.z, b0.w, b1.x, b1.y, b1.z, b1.w};
#pragma unroll
            for (int e = 0; e < 4; e++)
#pragma unroll
                for (int j = 0; j < 8; j++) acc[e][j] += av[e] * bv[j];
        }
        __syncthreads();
    }

    float* yo = out + (size_t)bh * 64 * NL + l0;
#pragma unroll
    for (int e = 0; e < 4; e++) {
        int o = ty * 4 + e;
        *(float4*)&yo[(size_t)o * NL + tx * 4]      = make_float4(acc[e][0], acc[e][1], acc[e][2], acc[e][3]);
        *(float4*)&yo[(size_t)o * NL + 64 + tx * 4] = make_float4(acc[e][4], acc[e][5], acc[e][6], acc[e][7]);
    }
}

// ---------------- launch ----------------
extern "C" void kernel_launch(void* const* d_in, const int* in_sizes, int n_in,
                              void* d_out, int out_size) {
    const float* q     = (const float*)d_in[0];
    // d_in[1] = k, d_in[2] = v : unused by FourierBlock
    const float* wreal = (const float*)d_in[3];
    const float* wimag = (const float*)d_in[4];
    const int*   index = (const int*)d_in[5];
    float* out = (float*)d_out;

    k_basis<<<(NL * 128 + 255) / 256, 256>>>(index);
    k_wt<<<NH * NE, 256>>>(wreal, wimag);
    k_fwd<<<dim3(NB * NH, 2), 256>>>(q);
    k_mix<<<NH * NM, 256>>>();
    k_inv<<<dim3(NB * NH, 16), 256>>>(out);
}

// round 7
// speedup vs baseline: 1.8943x; 1.8943x over previous
#include <cuda_runtime.h>
#include <cuda_bf16.h>
#include <cstdint>

// FourierBlock B=32 L=2048 H=8 E=64 M=64 — mma.sync (HMMA) bf16 split version.
// Harness compiles -arch=sm_100 (no 'a'): tcgen05 unavailable; mma.sync is arch-neutral.
//  K1: X[bh][k=128(re|im)][i=64] = FB[k][l] @ q[b,:,h,:]   (K=2048)
//  K2: O2[bh][k][o] complex mix with W (fp32 FFMA), emits bf16 hi/lo [k][o]
//  K3: y[bh][o][l]  = O2^T[o][k] @ IB^T[k][l]              (K=128)
// All big GEMMs: 3-term bf16 hi/lo split (hh + hl + lh), fp32 accumulate.

#define NL 2048

__device__ unsigned short g_FBh[128 * NL], g_FBl[128 * NL];   // [k][l]
__device__ unsigned short g_IBh[NL * 128], g_IBl[NL * 128];   // [l][k]
__device__ float g_WtR[8 * 64 * 64 * 64], g_WtI[8 * 64 * 64 * 64]; // [h][m][i][o]
__device__ float g_XF[256 * 128 * 64];                        // [bh][k][i]
__device__ unsigned g_O2h[256 * 128 * 32], g_O2l[256 * 128 * 32]; // [bh][k][o/2] bf16x2

// ---------------- helpers ----------------
__device__ __forceinline__ unsigned s2u(const void* p) {
    unsigned a;
    asm("{ .reg .u64 t; cvta.to.shared.u64 t, %1; cvt.u32.u64 %0, t; }" : "=r"(a) : "l"(p));
    return a;
}
__device__ __forceinline__ void ldm_x4(unsigned addr, unsigned* r) {
    asm volatile("ldmatrix.sync.aligned.m8n8.x4.shared.b16 {%0,%1,%2,%3}, [%4];"
        : "=r"(r[0]), "=r"(r[1]), "=r"(r[2]), "=r"(r[3]) : "r"(addr));
}
__device__ __forceinline__ void ldm_x4t(unsigned addr, unsigned* r) {
    asm volatile("ldmatrix.sync.aligned.m8n8.x4.trans.shared.b16 {%0,%1,%2,%3}, [%4];"
        : "=r"(r[0]), "=r"(r[1]), "=r"(r[2]), "=r"(r[3]) : "r"(addr));
}
__device__ __forceinline__ void ldm_x2(unsigned addr, unsigned* r) {
    asm volatile("ldmatrix.sync.aligned.m8n8.x2.shared.b16 {%0,%1}, [%2];"
        : "=r"(r[0]), "=r"(r[1]) : "r"(addr));
}
__device__ __forceinline__ void ldm_x2t(unsigned addr, unsigned* r) {
    asm volatile("ldmatrix.sync.aligned.m8n8.x2.trans.shared.b16 {%0,%1}, [%2];"
        : "=r"(r[0]), "=r"(r[1]) : "r"(addr));
}
__device__ __forceinline__ void mma_bf16(float* c, const unsigned* a, const unsigned* b) {
    asm volatile("mma.sync.aligned.m16n8k16.row.col.f32.bf16.bf16.f32 "
        "{%0,%1,%2,%3}, {%4,%5,%6,%7}, {%8,%9}, {%0,%1,%2,%3};"
        : "+f"(c[0]), "+f"(c[1]), "+f"(c[2]), "+f"(c[3])
        : "r"(a[0]), "r"(a[1]), "r"(a[2]), "r"(a[3]), "r"(b[0]), "r"(b[1]));
}
// split fp32 pair -> bf16x2 hi word + lo word
__device__ __forceinline__ void hl2(float x0, float x1, unsigned& hw, unsigned& lw) {
    __nv_bfloat16 a0 = __float2bfloat16_rn(x0), a1 = __float2bfloat16_rn(x1);
    float l0 = x0 - __bfloat162float(a0), l1 = x1 - __bfloat162float(a1);
    __nv_bfloat16 b0 = __float2bfloat16_rn(l0), b1 = __float2bfloat16_rn(l1);
    hw = (unsigned)__bfloat16_as_ushort(a0) | ((unsigned)__bfloat16_as_ushort(a1) << 16);
    lw = (unsigned)__bfloat16_as_ushort(b0) | ((unsigned)__bfloat16_as_ushort(b1) << 16);
}

// ---------------- K0a: basis tables (bf16 hi/lo) ----------------
__global__ __launch_bounds__(256) void k_basis(const int* __restrict__ index) {
    int t = blockIdx.x * 256 + threadIdx.x;    // 0..262143
    float s, c;
    {   // FB [k][l]: k<64 cos, k>=64 -sin, freq=index[k&63]
        int k = t >> 11, l = t & 2047, kf = k & 63;
        int p = (index[kf] * l) & 2047;
        sincospif((float)p * (1.0f / 1024.0f), &s, &c);
        float v = (k < 64) ? c : -s;
        __nv_bfloat16 h = __float2bfloat16_rn(v);
        g_FBh[t] = __bfloat16_as_ushort(h);
        g_FBl[t] = __bfloat16_as_ushort(__float2bfloat16_rn(v - __bfloat162float(h)));
    }
    {   // IB [l][k]: amp-folded irfft basis (modes in slots 0..63)
        int l = t >> 7, k = t & 127, kf = k & 63;
        int p = (kf * l) & 2047;
        sincospif((float)p * (1.0f / 1024.0f), &s, &c);
        float amp = (kf == 0) ? ((k < 64) ? (1.0f / (float)NL) : 0.0f) : (2.0f / (float)NL);
        float v = (k < 64) ? amp * c : -amp * s;
        __nv_bfloat16 h = __float2bfloat16_rn(v);
        g_IBh[t] = __bfloat16_as_ushort(h);
        g_IBl[t] = __bfloat16_as_ushort(__float2bfloat16_rn(v - __bfloat162float(h)));
    }
}

// ---------------- K0b: transpose W [h][i][o][m] -> [h][m][i][o] ----------------
__global__ __launch_bounds__(256) void k_wt(const float* __restrict__ wr, const float* __restrict__ wi) {
    __shared__ float sm[64][65];
    int h = blockIdx.x >> 6, i = blockIdx.x & 63, t = threadIdx.x;
    const float* src = wr + (size_t)((h * 64 + i) * 64) * 64;
    float* dst = g_WtR;
#pragma unroll
    for (int pass = 0; pass < 2; pass++) {
#pragma unroll
        for (int r = 0; r < 16; r++) { int u = r * 256 + t; sm[u >> 6][u & 63] = src[u]; }
        __syncthreads();
#pragma unroll
        for (int r = 0; r < 16; r++) {
            int u = r * 256 + t, m = u >> 6, o = u & 63;
            dst[(size_t)((h * 64 + m) * 64 + i) * 64 + o] = sm[o][m];
        }
        __syncthreads();
        src = wi + (size_t)((h * 64 + i) * 64) * 64;
        dst = g_WtI;
    }
}

// ---------------- K1: forward DFT, mma.sync ----------------
// CTA per bh. M=128 modes, N=64 i, K=2048 in 64 chunks of 32. 8 warps 4x2, warp 32x32.
// smem: Ah[2][128][40]b16 @0 (20480), Al @20480, Bh[2][32][72]b16 @40960 (9216), Bl @50176. tot 59392.
__global__ __launch_bounds__(256, 2) void k_fwd(const float* __restrict__ q) {
    extern __shared__ __align__(16) char sm[];
    unsigned sb = s2u(sm);
    int tid = threadIdx.x, lane = tid & 31, w = tid >> 5;
    int bh = blockIdx.x, b = bh >> 3, h = bh & 7;
    const float* qb = q + (size_t)b * NL * 512 + h * 64;
    int wm = w & 3, wn = w >> 2;
    int lq = tid >> 3, iq = (tid & 7) * 8;

    auto stageA = [&](int buf, int l0) {
#pragma unroll
        for (int rpt = 0; rpt < 2; rpt++) {
            int u = rpt * 256 + tid;             // 512 units of 16B
            int m = u >> 2, seg = u & 3;
            unsigned off = (unsigned)buf * 10240 + m * 80 + seg * 16;
            *(uint4*)(sm + off)         = *(const uint4*)(g_FBh + (size_t)m * NL + l0 + seg * 8);
            *(uint4*)(sm + 20480 + off) = *(const uint4*)(g_FBl + (size_t)m * NL + l0 + seg * 8);
        }
    };
    auto stageB = [&](int buf, int l0) {
        const float* src = qb + (size_t)(l0 + lq) * 512 + iq;
        float4 v0 = *(const float4*)src, v1 = *(const float4*)(src + 4);
        unsigned h0, l0w, h1, l1, h2, l2, h3, l3;
        hl2(v0.x, v0.y, h0, l0w); hl2(v0.z, v0.w, h1, l1);
        hl2(v1.x, v1.y, h2, l2);  hl2(v1.z, v1.w, h3, l3);
        unsigned off = (unsigned)buf * 4608 + lq * 144 + iq * 2;
        *(uint4*)(sm + 40960 + off) = make_uint4(h0, h1, h2, h3);
        *(uint4*)(sm + 50176 + off) = make_uint4(l0w, l1, l2, l3);
    };

    float c[2][4][4] = {};
    stageA(0, 0); stageB(0, 0);
    __syncthreads();
    for (int ch = 0; ch < 64; ch++) {
        int buf = ch & 1;
        if (ch + 1 < 64) { stageA(buf ^ 1, (ch + 1) * 32); stageB(buf ^ 1, (ch + 1) * 32); }
#pragma unroll
        for (int ks = 0; ks < 2; ks++) {
            unsigned ah[2][4], al[2][4], bhf[4][2], blf[4][2];
#pragma unroll
            for (int mt = 0; mt < 2; mt++) {
                unsigned row = wm * 32 + mt * 16 + (lane & 7) + ((lane >> 3) & 1) * 8;
                unsigned col = ks * 16 + ((lane >> 4) & 1) * 8;
                unsigned off = (unsigned)buf * 10240 + row * 80 + col * 2;
                ldm_x4(sb + off, ah[mt]);
                ldm_x4(sb + 20480 + off, al[mt]);
            }
#pragma unroll
            for (int nt = 0; nt < 4; nt++) {
                unsigned row = ks * 16 + (lane & 15);
                unsigned off = (unsigned)buf * 4608 + row * 144 + (wn * 32 + nt * 8) * 2;
                ldm_x2t(sb + 40960 + off, bhf[nt]);
                ldm_x2t(sb + 50176 + off, blf[nt]);
            }
#pragma unroll
            for (int mt = 0; mt < 2; mt++)
#pragma unroll
                for (int nt = 0; nt < 4; nt++) {
                    mma_bf16(c[mt][nt], ah[mt], bhf[nt]);
                    mma_bf16(c[mt][nt], ah[mt], blf[nt]);
                    mma_bf16(c[mt][nt], al[mt], bhf[nt]);
                }
        }
        __syncthreads();
    }
    float* xf = g_XF + (size_t)bh * 128 * 64;
#pragma unroll
    for (int mt = 0; mt < 2; mt++) {
        int m0 = wm * 32 + mt * 16 + (lane >> 2);
#pragma unroll
        for (int nt = 0; nt < 4; nt++) {
            int n = wn * 32 + nt * 8 + 2 * (lane & 3);
            *(float2*)&xf[(size_t)m0 * 64 + n]       = make_float2(c[mt][nt][0], c[mt][nt][1]);
            *(float2*)&xf[(size_t)(m0 + 8) * 64 + n] = make_float2(c[mt][nt][2], c[mt][nt][3]);
        }
    }
}

// ---------------- K2: complex mode mixing, emits bf16 hi/lo O2 [k][o] ----------------
__global__ __launch_bounds__(64) void k_mix() {
    __shared__ float Xr[32][64], Xi[32][64];
    __shared__ float Wr[64][64], Wi[64][64];
    int h = blockIdx.x >> 6, m = blockIdx.x & 63, t = threadIdx.x;
#pragma unroll
    for (int p = 0; p < 8; p++) {
        int u = p * 64 + t, b = u >> 4, i4 = (u & 15) * 4;
        size_t base = ((size_t)(b * 8 + h) * 128 + m) * 64;
        *(float4*)&Xr[b][i4] = *(const float4*)&g_XF[base + i4];
        *(float4*)&Xi[b][i4] = *(const float4*)&g_XF[base + 4096 + i4];
    }
#pragma unroll
    for (int p = 0; p < 16; p++) {
        int u = p * 64 + t, i = u >> 4, o4 = (u & 15) * 4;
        size_t base = (size_t)((h * 64 + m) * 64 + i) * 64;
        *(float4*)&Wr[i][o4] = *(const float4*)&g_WtR[base + o4];
        *(float4*)&Wi[i][o4] = *(const float4*)&g_WtI[base + o4];
    }
    __syncthreads();
    int og = (t & 15) * 4, bg = (t >> 4) * 8;
    float ar[8][4], ai[8][4];
#pragma unroll
    for (int j = 0; j < 8; j++)
#pragma unroll
        for (int cc = 0; cc < 4; cc++) { ar[j][cc] = 0.0f; ai[j][cc] = 0.0f; }
    for (int i = 0; i < 64; i++) {
        float wr[4], wv[4];
#pragma unroll
        for (int cc = 0; cc < 4; cc++) { wr[cc] = Wr[i][og + cc]; wv[cc] = Wi[i][og + cc]; }
#pragma unroll
        for (int j = 0; j < 8; j++) {
            float xr = Xr[bg + j][i], xi = Xi[bg + j][i];
#pragma unroll
            for (int cc = 0; cc < 4; cc++) {
                ar[j][cc] += xr * wr[cc] - xi * wv[cc];
                ai[j][cc] += xr * wv[cc] + xi * wr[cc];
            }
        }
    }
#pragma unroll
    for (int j = 0; j < 8; j++) {
        int bh = (bg + j) * 8 + h;
        unsigned h0, l0, h1, l1;
        size_t w0 = ((size_t)bh * 128 + m) * 32 + og / 2;
        hl2(ar[j][0], ar[j][1], h0, l0); hl2(ar[j][2], ar[j][3], h1, l1);
        g_O2h[w0] = h0; g_O2h[w0 + 1] = h1; g_O2l[w0] = l0; g_O2l[w0 + 1] = l1;
        size_t w1 = ((size_t)bh * 128 + 64 + m) * 32 + og / 2;
        hl2(ai[j][0], ai[j][1], h0, l0); hl2(ai[j][2], ai[j][3], h1, l1);
        g_O2h[w1] = h0; g_O2h[w1 + 1] = h1; g_O2l[w1] = l0; g_O2l[w1 + 1] = l1;
    }
}

// ---------------- K3: inverse, mma.sync ----------------
// CTA = (bh-group of 4) x (l-tile of 128). M=o(64), N=l(128), K=128. 8 warps 2x4, warp 32x32.
// A = O2 [k][o] via ldmatrix.x4.trans; B = IB [l][k] via ldmatrix.x2; C[o][l] coalesced stores.
// smem: Bh(IB)[128][136]b16 @0 (34816), Bl @34816, Ah(O2)[128][72]b16 @69632 (18432), Al @88064. tot 106496.
__global__ __launch_bounds__(256, 1) void k_inv(float* __restrict__ out) {
    extern __shared__ __align__(16) char sm[];
    unsigned sb = s2u(sm);
    int tid = threadIdx.x, lane = tid & 31, w = tid >> 5;
    int g = blockIdx.x & 63, lt = blockIdx.x >> 6;
    int wm = w & 1, wn = w >> 1;

    // stage B (IB) once: [128 l][128 k] hi/lo
#pragma unroll
    for (int rpt = 0; rpt < 8; rpt++) {
        int u = rpt * 256 + tid;                 // 2048 units of 16B
        int l = u >> 4, seg = u & 15;
        unsigned off = l * 272 + seg * 16;
        *(uint4*)(sm + off)         = *(const uint4*)(g_IBh + (size_t)(lt * 128 + l) * 128 + seg * 8);
        *(uint4*)(sm + 34816 + off) = *(const uint4*)(g_IBl + (size_t)(lt * 128 + l) * 128 + seg * 8);
    }
    for (int bj = 0; bj < 4; bj++) {
        int bh = g * 4 + bj;
        __syncthreads();                         // A free (prev compute done) / B visible on bj==0
#pragma unroll
        for (int rpt = 0; rpt < 4; rpt++) {
            int u = rpt * 256 + tid;             // 1024 units of 16B
            int k = u >> 3, seg = u & 7;
            unsigned off = k * 144 + seg * 16;
            *(uint4*)(sm + 69632 + off) = *(const uint4*)(g_O2h + (size_t)bh * 4096 + k * 32 + seg * 4);
            *(uint4*)(sm + 88064 + off) = *(const uint4*)(g_O2l + (size_t)bh * 4096 + k * 32 + seg * 4);
        }
        __syncthreads();
        float c[2][4][4] = {};
#pragma unroll
        for (int ks = 0; ks < 8; ks++) {
            int k0 = ks * 16;
            unsigned ah[2][4], al[2][4], bhf[4][2], blf[4][2];
#pragma unroll
            for (int mt = 0; mt < 2; mt++) {
                unsigned row = k0 + (lane & 7) + ((lane >> 4) & 1) * 8;
                unsigned col = wm * 32 + mt * 16 + ((lane >> 3) & 1) * 8;
                unsigned off = row * 144 + col * 2;
                ldm_x4t(sb + 69632 + off, ah[mt]);
                ldm_x4t(sb + 88064 + off, al[mt]);
            }
#pragma unroll
            for (int nt = 0; nt < 4; nt++) {
                unsigned row = wn * 32 + nt * 8 + (lane & 7);
                unsigned col = k0 + ((lane >> 3) & 1) * 8;
                unsigned off = row * 272 + col * 2;
                ldm_x2(sb + off, bhf[nt]);
                ldm_x2(sb + 34816 + off, blf[nt]);
            }
#pragma unroll
            for (int mt = 0; mt < 2; mt++)
#pragma unroll
                for (int nt = 0; nt < 4; nt++) {
                    mma_bf16(c[mt][nt], ah[mt], bhf[nt]);
                    mma_bf16(c[mt][nt], ah[mt], blf[nt]);
                    mma_bf16(c[mt][nt], al[mt], bhf[nt]);
                }
        }
        float* yb = out + (size_t)bh * 64 * NL + lt * 128;
#pragma unroll
        for (int mt = 0; mt < 2; mt++) {
            int o = wm * 32 + mt * 16 + (lane >> 2);
#pragma unroll
            for (int nt = 0; nt < 4; nt++) {
                int l = wn * 32 + nt * 8 + 2 * (lane & 3);
                *(float2*)&yb[(size_t)o * NL + l]       = make_float2(c[mt][nt][0], c[mt][nt][1]);
                *(float2*)&yb[(size_t)(o + 8) * NL + l] = make_float2(c[mt][nt][2], c[mt][nt][3]);
            }
        }
    }
}

// ---------------- launch ----------------
extern "C" void kernel_launch(void* const* d_in, const int* in_sizes, int n_in,
                              void* d_out, int out_size) {
    const float* q     = (const float*)d_in[0];
    const float* wreal = (const float*)d_in[3];
    const float* wimag = (const float*)d_in[4];
    const int*   index = (const int*)d_in[5];
    float* out = (float*)d_out;

    cudaFuncSetAttribute(k_fwd, cudaFuncAttributeMaxDynamicSharedMemorySize, 59392);
    cudaFuncSetAttribute(k_inv, cudaFuncAttributeMaxDynamicSharedMemorySize, 106496);

    k_basis<<<1024, 256>>>(index);
    k_wt<<<512, 256>>>(wreal, wimag);
    k_fwd<<<256, 256, 59392>>>(q);
    k_mix<<<512, 64>>>();
    k_inv<<<1024, 256, 106496>>>(out);
}